// round 11
// baseline (speedup 1.0000x reference)
#include <cuda_runtime.h>
#include <stdint.h>

#define NUM_OBJ_CLS 151
#define NUM_REL_CLS 51

// Per-iteration row/col bases for k = 0..50: jb = (32k)/51, cb = (32k)%51.
// Warp-uniform index -> LDCU (uniform pipe), replacing per-lane mulhi div.
// Lane adjust: f = 32k+lane = 51*jb + cb + lane; cb+lane <= 81 < 102 so at
// most one wrap: j = jb + (cb+lane >= 51), c = cb+lane - (wrap ? 51 : 0).
__constant__ int c_jb[NUM_REL_CLS] = {
    0,0,1,1,2,3,3,4,5,5,6,6,7,8,8,9,10,10,11,11,12,13,13,14,15,15,16,16,
    17,18,18,19,20,20,21,21,22,23,23,24,25,25,26,26,27,28,28,29,30,30,31};
__constant__ int c_cb[NUM_REL_CLS] = {
    0,32,13,45,26,7,39,20,1,33,14,46,27,8,40,21,2,34,15,47,28,9,41,22,3,
    35,16,48,29,10,42,23,4,36,17,49,30,11,43,24,5,37,18,50,31,12,44,25,6,38,19};

// ---------------------------------------------------------------------------
// Fused kernel. Section 1: obj_dists = exact one-hot (softmax of +/-1000
// fp32 logits underflows to one-hot). Section 2: rel gather — warp = 32
// pairs = 1632 floats = 51 dense stride-1 warp iterations, load index space
// == store index space (no staging), (j,c) via constant LUT, next chunk's
// pair->label->label chain software-pipelined across the copy loop.
// ---------------------------------------------------------------------------
__global__ void __launch_bounds__(256, 8)
fused_kernel(const int* __restrict__ labels,
             const int2* __restrict__ pairs,
             const float* __restrict__ table,
             float* __restrict__ obj_out,
             float* __restrict__ rel_out,
             int n_obj, int n_pairs) {
    const int tid_global = blockIdx.x * blockDim.x + threadIdx.x;
    const int n_threads  = gridDim.x * blockDim.x;

    // ---- Section 1: one-hot. ----
    {
        const int n_floats = n_obj * NUM_OBJ_CLS;
        const int n_vec = n_floats >> 2;
        for (int i = tid_global; i < n_vec; i += n_threads) {
            int f0 = i * 4;
            float4 v;
            #pragma unroll
            for (int k = 0; k < 4; k++) {
                int f = f0 + k;
                int r = f / NUM_OBJ_CLS, c = f - r * NUM_OBJ_CLS;
                float val = (__ldg(&labels[r]) == c) ? 1.0f : 0.0f;
                if (k == 0) v.x = val; else if (k == 1) v.y = val;
                else if (k == 2) v.z = val; else v.w = val;
            }
            *(float4*)(obj_out + f0) = v;
        }
        if (tid_global == 0) {
            for (int f = n_vec * 4; f < n_floats; f++) {
                int r = f / NUM_OBJ_CLS, c = f - r * NUM_OBJ_CLS;
                obj_out[f] = (__ldg(&labels[r]) == c) ? 1.0f : 0.0f;
            }
        }
    }

    // ---- Section 2: rel gather, pipelined across chunks. ----
    const int lane = threadIdx.x & 31;
    const int warp_id   = tid_global >> 5;
    const int num_warps = n_threads >> 5;
    const int n_chunks  = n_pairs >> 5;

    int chunk = warp_id;
    int h = 0, t = 0;
    if (chunk < n_chunks) {
        int2 pr = __ldg(&pairs[(chunk << 5) + lane]);
        h = __ldg(&labels[pr.x]);
        t = __ldg(&labels[pr.y]);
    }

    while (chunk < n_chunks) {
        const int base = (h * NUM_OBJ_CLS + t) * NUM_REL_CLS;
        const int next = chunk + num_warps;

        // Prefetch next chunk's pair row (lands during the copy loop).
        int2 pr_n = make_int2(0, 0);
        if (next < n_chunks) pr_n = __ldg(&pairs[(next << 5) + lane]);

        float* __restrict__ dst = rel_out + (size_t)(chunk << 5) * NUM_REL_CLS;

        // First half: k = 0..23.
        #pragma unroll 6
        for (int k = 0; k < 24; k++) {
            int fl = c_cb[k] + lane;                 // LDCU + IADD
            int wrap = (fl >= NUM_REL_CLS);
            int j = c_jb[k] + wrap;
            int c = fl - (wrap ? NUM_REL_CLS : 0);
            int b = __shfl_sync(0xffffffffu, base, j);
            __stcs(dst + k * 32 + lane, __ldg(table + b + c));
        }

        // Resolve next chunk's labels; overlaps with second half.
        if (next < n_chunks) {
            h = __ldg(&labels[pr_n.x]);
            t = __ldg(&labels[pr_n.y]);
        }

        // Second half: k = 24..50.
        #pragma unroll 6
        for (int k = 24; k < NUM_REL_CLS; k++) {
            int fl = c_cb[k] + lane;
            int wrap = (fl >= NUM_REL_CLS);
            int j = c_jb[k] + wrap;
            int c = fl - (wrap ? NUM_REL_CLS : 0);
            int b = __shfl_sync(0xffffffffu, base, j);
            __stcs(dst + k * 32 + lane, __ldg(table + b + c));
        }

        chunk = next;
    }

    // Leftover pairs (n_pairs % 32): absent for 2M pairs, kept for generality.
    if (warp_id == 0) {
        for (int p = n_chunks << 5; p < n_pairs; p++) {
            int2 pr = __ldg(&pairs[p]);
            int hh = __ldg(&labels[pr.x]);
            int tt = __ldg(&labels[pr.y]);
            int b = (hh * NUM_OBJ_CLS + tt) * NUM_REL_CLS;
            float* __restrict__ dstp = rel_out + (size_t)p * NUM_REL_CLS;
            if (lane < NUM_REL_CLS) dstp[lane] = __ldg(table + b + lane);
            if (lane < NUM_REL_CLS - 32) dstp[32 + lane] = __ldg(table + b + 32 + lane);
        }
    }
}

extern "C" void kernel_launch(void* const* d_in, const int* in_sizes, int n_in,
                              void* d_out, int out_size) {
    const int*   labels = (const int*)d_in[0];          // [N_OBJ] int32
    const int2*  pairs  = (const int2*)d_in[1];         // [N_PAIRS, 2] int32
    const float* table  = (const float*)d_in[2];        // [151,151,51] f32

    const int n_obj   = in_sizes[0];
    const int n_pairs = in_sizes[1] / 2;

    float* obj_out = (float*)d_out;                               // [n_obj, 151]
    float* rel_out = obj_out + (size_t)n_obj * NUM_OBJ_CLS;       // [n_pairs, 51]

    // Persistent single wave on GB300: 152 SMs x 8 resident blocks.
    fused_kernel<<<1216, 256>>>(labels, pairs, table, obj_out, rel_out,
                                n_obj, n_pairs);
}